// round 2
// baseline (speedup 1.0000x reference)
#include <cuda_runtime.h>
#include <cstdint>

#define NUM_E 1024
#define EDIM  256
#define BATCH 32
#define HW    1024          // 32*32
#define NROWS (BATCH*HW)    // 32768

// Scratch (no allocations allowed)
__device__ float g_cbnorm[NUM_E];          // ||e_k||^2
__device__ float g_cbT[EDIM * NUM_E];      // codebook transposed [c][k]
__device__ int   g_argmin[NROWS];

// ---------- packed f32x2 helpers (Blackwell) ----------
__device__ __forceinline__ unsigned long long pack2(float x, float y) {
    unsigned long long r;
    asm("mov.b64 %0, {%1, %2};" : "=l"(r) : "f"(x), "f"(y));
    return r;
}
__device__ __forceinline__ unsigned long long fma2(unsigned long long a,
                                                   unsigned long long b,
                                                   unsigned long long c) {
    unsigned long long d;
    asm("fma.rn.f32x2 %0, %1, %2, %3;" : "=l"(d) : "l"(a), "l"(b), "l"(c));
    return d;
}
__device__ __forceinline__ float lo32(unsigned long long u) {
    return __uint_as_float((unsigned)(u & 0xffffffffull));
}
__device__ __forceinline__ float hi32(unsigned long long u) {
    return __uint_as_float((unsigned)(u >> 32));
}

// ---------- prep: codebook norms + transpose ----------
__global__ __launch_bounds__(256) void prep_kernel(const float* __restrict__ cb) {
    int k = blockIdx.x;       // 0..1023
    int t = threadIdx.x;      // 0..255
    float v = cb[(size_t)k * EDIM + t];
    g_cbT[(size_t)t * NUM_E + k] = v;
    float sq = v * v;
    // warp reduce
    #pragma unroll
    for (int off = 16; off; off >>= 1)
        sq += __shfl_down_sync(0xffffffffu, sq, off);
    __shared__ float ws[8];
    int lane = t & 31, wid = t >> 5;
    if (lane == 0) ws[wid] = sq;
    __syncthreads();
    if (t == 0) {
        float s = 0.f;
        #pragma unroll
        for (int i = 0; i < 8; i++) s += ws[i];
        g_cbnorm[k] = s;
    }
}

// ---------- main: fused GEMM (f32x2) + argmin ----------
// Grid: NROWS/64 = 512 blocks, 256 threads.
// Block tile: M=64 rows x Ktile=128 codewords, C chunked by 8.
__global__ __launch_bounds__(256) void vq_argmin_kernel(const float* __restrict__ z,
                                                        const float* __restrict__ cb) {
    __shared__ __align__(16) float As[8][64];
    __shared__ __align__(16) float Bs[8][132];   // stride 132 -> conflict-free stores, 16B-aligned rows

    const int t  = threadIdx.x;
    const int tx = t & 15;        // col group: cols tx*8 .. tx*8+7
    const int ty = t >> 4;        // row group: rows ty*4 .. ty*4+3
    const int n0 = blockIdx.x * 64;
    const int b  = n0 >> 10;
    const int hw0 = n0 & 1023;
    const float* zb = z + (size_t)b * (EDIM * HW) + hw0;   // zb[c*1024 + i]

    float minv[4]; int mink[4];
    #pragma unroll
    for (int i = 0; i < 4; i++) { minv[i] = 3.4e38f; mink[i] = 0; }

    for (int k0 = 0; k0 < NUM_E; k0 += 128) {
        unsigned long long acc[4][4];
        #pragma unroll
        for (int i = 0; i < 4; i++)
            #pragma unroll
            for (int p = 0; p < 4; p++) acc[i][p] = 0ull;

        float cbn[8];
        #pragma unroll
        for (int j = 0; j < 8; j++) cbn[j] = __ldg(&g_cbnorm[k0 + tx * 8 + j]);

        for (int c0 = 0; c0 < EDIM; c0 += 8) {
            __syncthreads();
            // A tile: 8 c-rows x 64 cols (coalesced, 2 elems/thread)
            {
                int e0 = t;
                As[e0 >> 6][e0 & 63] = zb[(size_t)(c0 + (e0 >> 6)) * HW + (e0 & 63)];
                int e1 = t + 256;
                As[e1 >> 6][e1 & 63] = zb[(size_t)(c0 + (e1 >> 6)) * HW + (e1 & 63)];
            }
            // B tile: 128 k x 8 c (float4 per thread), stored transposed Bs[c][k]
            {
                int kk = t >> 1;
                int coff = (t & 1) * 4;
                float4 v = *(const float4*)&cb[(size_t)(k0 + kk) * EDIM + c0 + coff];
                Bs[coff + 0][kk] = v.x;
                Bs[coff + 1][kk] = v.y;
                Bs[coff + 2][kk] = v.z;
                Bs[coff + 3][kk] = v.w;
            }
            __syncthreads();
            #pragma unroll
            for (int cc = 0; cc < 8; cc++) {
                float4 a4 = *(const float4*)&As[cc][ty * 4];
                ulonglong2 b01 = *(const ulonglong2*)&Bs[cc][tx * 8];
                ulonglong2 b23 = *(const ulonglong2*)&Bs[cc][tx * 8 + 4];
                unsigned long long av0 = pack2(a4.x, a4.x);
                unsigned long long av1 = pack2(a4.y, a4.y);
                unsigned long long av2 = pack2(a4.z, a4.z);
                unsigned long long av3 = pack2(a4.w, a4.w);
                acc[0][0] = fma2(av0, b01.x, acc[0][0]);
                acc[0][1] = fma2(av0, b01.y, acc[0][1]);
                acc[0][2] = fma2(av0, b23.x, acc[0][2]);
                acc[0][3] = fma2(av0, b23.y, acc[0][3]);
                acc[1][0] = fma2(av1, b01.x, acc[1][0]);
                acc[1][1] = fma2(av1, b01.y, acc[1][1]);
                acc[1][2] = fma2(av1, b23.x, acc[1][2]);
                acc[1][3] = fma2(av1, b23.y, acc[1][3]);
                acc[2][0] = fma2(av2, b01.x, acc[2][0]);
                acc[2][1] = fma2(av2, b01.y, acc[2][1]);
                acc[2][2] = fma2(av2, b23.x, acc[2][2]);
                acc[2][3] = fma2(av2, b23.y, acc[2][3]);
                acc[3][0] = fma2(av3, b01.x, acc[3][0]);
                acc[3][1] = fma2(av3, b01.y, acc[3][1]);
                acc[3][2] = fma2(av3, b23.x, acc[3][2]);
                acc[3][3] = fma2(av3, b23.y, acc[3][3]);
            }
        }

        // epilogue: d = ||e||^2 - 2*s ; local argmin over 8 cols (ascending k, strict <)
        #pragma unroll
        for (int i = 0; i < 4; i++) {
            float v = 3.4e38f; int vk = 0;
            #pragma unroll
            for (int p = 0; p < 4; p++) {
                float s0 = lo32(acc[i][p]);
                float s1 = hi32(acc[i][p]);
                float d0 = cbn[2 * p]     - 2.0f * s0;
                float d1 = cbn[2 * p + 1] - 2.0f * s1;
                int kbase = k0 + tx * 8 + 2 * p;
                if (d0 < v) { v = d0; vk = kbase; }
                if (d1 < v) { v = d1; vk = kbase + 1; }
            }
            // reduce across the 16 tx lanes (lower lane = smaller k wins ties)
            #pragma unroll
            for (int off = 8; off; off >>= 1) {
                float ov = __shfl_down_sync(0xffffffffu, v, off, 16);
                int   oi = __shfl_down_sync(0xffffffffu, vk, off, 16);
                if (ov < v) { v = ov; vk = oi; }
            }
            if (tx == 0) {
                if (v < minv[i]) { minv[i] = v; mink[i] = vk; }
            }
        }
    }

    if (tx == 0) {
        #pragma unroll
        for (int i = 0; i < 4; i++)
            g_argmin[n0 + ty * 4 + i] = mink[i];
    }
}

// ---------- outputs ----------
// one-hot rows: block per row, 256 threads x float4
__global__ __launch_bounds__(256) void onehot_kernel(float* __restrict__ out) {
    int r = blockIdx.x;
    int t = threadIdx.x;
    int idx = g_argmin[r];
    int c0 = t * 4;
    float4 v;
    v.x = (idx == c0 + 0) ? 1.0f : 0.0f;
    v.y = (idx == c0 + 1) ? 1.0f : 0.0f;
    v.z = (idx == c0 + 2) ? 1.0f : 0.0f;
    v.w = (idx == c0 + 3) ? 1.0f : 0.0f;
    *(float4*)&out[(size_t)r * NUM_E + c0] = v;
}

// z_quantized[b,c,hw] = cbT[c][argmin[b*1024+hw]]  (linear index == b*262144 + c*1024 + hw)
__global__ __launch_bounds__(256) void quant_kernel(float* __restrict__ outq) {
    int i = blockIdx.x * blockDim.x + threadIdx.x;   // float4 id, total 2097152
    int flat = i * 4;
    int hw = flat & 1023;
    int c  = (flat >> 10) & 255;
    int b  = flat >> 18;
    int4 idx4 = *(const int4*)&g_argmin[b * 1024 + hw];
    const float* row = &g_cbT[(size_t)c * NUM_E];
    float4 v;
    v.x = row[idx4.x];
    v.y = row[idx4.y];
    v.z = row[idx4.z];
    v.w = row[idx4.w];
    *(float4*)&outq[flat] = v;
}

extern "C" void kernel_launch(void* const* d_in, const int* in_sizes, int n_in,
                              void* d_out, int out_size) {
    const float* z  = (const float*)d_in[0];
    const float* cb = (const float*)d_in[1];
    float* out_onehot = (float*)d_out;
    float* out_q      = (float*)d_out + (size_t)NROWS * NUM_E;

    prep_kernel<<<NUM_E, 256>>>(cb);
    vq_argmin_kernel<<<NROWS / 64, 256>>>(z, cb);
    onehot_kernel<<<NROWS, 256>>>(out_onehot);
    quant_kernel<<<(NROWS * EDIM) / 4 / 256, 256>>>(out_q);
}

// round 5
// speedup vs baseline: 4.5449x; 4.5449x over previous
#include <cuda_runtime.h>
#include <cuda_bf16.h>
#include <cstdint>

#define NUM_E 1024
#define EDIM  256
#define NROWS 32768

// ---- device scratch ----
__device__ float g_cbnorm[NUM_E];
__device__ float g_cbT[EDIM * NUM_E];
__device__ unsigned long long g_key[NROWS];           // (ordfloat<<32)|idx
__device__ __nv_bfloat16 g_bsp[3][NUM_E * EDIM];      // codebook bf16 splits [sp][n][c]

// ---- smem layout (bytes) ----
#define AS_STRIDE 528            // 264 bf16 per c-row (256 + 8 pad)
#define AS_SPLIT  16896          // 32 c-rows * 528
#define AS_BUF    50688          // 3 splits
#define BS_OFF    101376
#define BS_SPLIT  10240          // 128 n-rows * 80
#define BS_BUF    30720
#define CBN_OFF   162816
#define KRED_OFF  163328         // 256 rows * 4 nwarps * 8B
#define SMEM_TOTAL 171520

__device__ __forceinline__ uint32_t smem_u32(const void* p) {
    uint32_t a;
    asm("{ .reg .u64 t; cvta.to.shared.u64 t, %1; cvt.u32.u64 %0, t; }" : "=r"(a) : "l"(p));
    return a;
}
__device__ __forceinline__ void cpasync16(uint32_t dst, const void* src) {
    asm volatile("cp.async.cg.shared.global [%0], [%1], 16;" :: "r"(dst), "l"(src));
}
__device__ __forceinline__ void ldsm_x4(uint32_t* r, uint32_t addr) {
    asm volatile("ldmatrix.sync.aligned.m8n8.x4.shared.b16 {%0,%1,%2,%3}, [%4];"
                 : "=r"(r[0]), "=r"(r[1]), "=r"(r[2]), "=r"(r[3]) : "r"(addr));
}
__device__ __forceinline__ void ldsm_x4t(uint32_t* r, uint32_t addr) {
    asm volatile("ldmatrix.sync.aligned.m8n8.x4.trans.shared.b16 {%0,%1,%2,%3}, [%4];"
                 : "=r"(r[0]), "=r"(r[1]), "=r"(r[2]), "=r"(r[3]) : "r"(addr));
}
__device__ __forceinline__ void mma16816(float* c, const uint32_t* a, uint32_t b0, uint32_t b1) {
    asm volatile("mma.sync.aligned.m16n8k16.row.col.f32.bf16.bf16.f32 "
                 "{%0,%1,%2,%3}, {%4,%5,%6,%7}, {%8,%9}, {%0,%1,%2,%3};"
                 : "+f"(c[0]), "+f"(c[1]), "+f"(c[2]), "+f"(c[3])
                 : "r"(a[0]), "r"(a[1]), "r"(a[2]), "r"(a[3]), "r"(b0), "r"(b1));
}
__device__ __forceinline__ unsigned ordf(float d) {
    unsigned u = __float_as_uint(d);
    return (u & 0x80000000u) ? ~u : (u | 0x80000000u);
}

// ---------- prep: norms + transpose + bf16 splits + key init ----------
__global__ __launch_bounds__(256) void prep_kernel(const float* __restrict__ cb) {
    int k = blockIdx.x, t = threadIdx.x;
    float v = cb[(size_t)k * EDIM + t];
    g_cbT[(size_t)t * NUM_E + k] = v;
    __nv_bfloat16 s0 = __float2bfloat16(v);  float r1 = v - __bfloat162float(s0);
    __nv_bfloat16 s1 = __float2bfloat16(r1); float r2 = r1 - __bfloat162float(s1);
    __nv_bfloat16 s2 = __float2bfloat16(r2);
    g_bsp[0][k * EDIM + t] = s0;
    g_bsp[1][k * EDIM + t] = s1;
    g_bsp[2][k * EDIM + t] = s2;
    if (t < 32) g_key[k * 32 + t] = ~0ull;
    float sq = v * v;
    #pragma unroll
    for (int o = 16; o; o >>= 1) sq += __shfl_down_sync(0xffffffffu, sq, o);
    __shared__ float ws[8];
    if ((t & 31) == 0) ws[t >> 5] = sq;
    __syncthreads();
    if (t == 0) {
        float s = 0.f;
        #pragma unroll
        for (int i = 0; i < 8; i++) s += ws[i];
        g_cbnorm[k] = s;
    }
}

// ---------- main: bf16 mma.sync GEMM + fused argmin ----------
// grid = 1024 (128 mtiles x 8 ntiles), block = 512
__global__ __launch_bounds__(512, 1) void vq_mma_kernel(const float* __restrict__ z) {
    extern __shared__ __align__(16) unsigned char smem[];
    const uint32_t sb = smem_u32(smem);
    const int tid = threadIdx.x;
    const int lane = tid & 31;
    const int w = tid >> 5, wm = w & 3, wn = w >> 2;
    const int ntile = blockIdx.x & 7, mtile = blockIdx.x >> 3;
    const int m0 = mtile * 256, n0 = ntile * 128;
    const float* zbase = z + (size_t)(m0 >> 10) * (EDIM * 1024) + (m0 & 1023);

    if (tid < 128) ((float*)(smem + CBN_OFF))[tid] = g_cbnorm[n0 + tid];

    float acc[4][4][4];
    #pragma unroll
    for (int i = 0; i < 4; i++)
        #pragma unroll
        for (int j = 0; j < 4; j++)
            #pragma unroll
            for (int e = 0; e < 4; e++) acc[i][j][e] = 0.f;

    // per-thread load roles
    const int cr = tid >> 4, cm = (tid & 15) * 16;     // A: c-row, m-range
    const int bn = tid >> 2, bseg = tid & 3;           // B: n-row, 16B seg

    // ---- chunk 0: issue B, store A ----
    {
        #pragma unroll
        for (int q = 0; q < 3; q++)
            cpasync16(sb + BS_OFF + q * BS_SPLIT + bn * 80 + bseg * 16,
                      &g_bsp[q][(size_t)(n0 + bn) * EDIM + bseg * 8]);
        asm volatile("cp.async.commit_group;");
    }
    #pragma unroll 1
    for (int pre = 0; pre < 1; pre++) {
        const float4* src = (const float4*)(zbase + (size_t)cr * 1024 + cm);
        #pragma unroll
        for (int q = 0; q < 4; q++) {
            float4 f = src[q];
            float xs[4] = {f.x, f.y, f.z, f.w};
            __nv_bfloat16 p0[4], p1[4], p2[4];
            #pragma unroll
            for (int e = 0; e < 4; e++) {
                p0[e] = __float2bfloat16(xs[e]); float r = xs[e] - __bfloat162float(p0[e]);
                p1[e] = __float2bfloat16(r);     r = r - __bfloat162float(p1[e]);
                p2[e] = __float2bfloat16(r);
            }
            uint32_t off = cr * AS_STRIDE + cm * 2 + q * 8;
            __nv_bfloat162 v;
            v = __halves2bfloat162(p0[0], p0[1]); *(uint32_t*)(smem + 0 * AS_SPLIT + off)     = *(uint32_t*)&v;
            v = __halves2bfloat162(p0[2], p0[3]); *(uint32_t*)(smem + 0 * AS_SPLIT + off + 4) = *(uint32_t*)&v;
            v = __halves2bfloat162(p1[0], p1[1]); *(uint32_t*)(smem + 1 * AS_SPLIT + off)     = *(uint32_t*)&v;
            v = __halves2bfloat162(p1[2], p1[3]); *(uint32_t*)(smem + 1 * AS_SPLIT + off + 4) = *(uint32_t*)&v;
            v = __halves2bfloat162(p2[0], p2[1]); *(uint32_t*)(smem + 2 * AS_SPLIT + off)     = *(uint32_t*)&v;
            v = __halves2bfloat162(p2[2], p2[3]); *(uint32_t*)(smem + 2 * AS_SPLIT + off + 4) = *(uint32_t*)&v;
        }
    }

    #pragma unroll 1
    for (int ch = 0; ch < 8; ch++) {
        const int buf = ch & 1;
        if (ch < 7) {
            const int c0 = (ch + 1) * 32, nbuf = buf ^ 1;
            #pragma unroll
            for (int q = 0; q < 3; q++)
                cpasync16(sb + BS_OFF + nbuf * BS_BUF + q * BS_SPLIT + bn * 80 + bseg * 16,
                          &g_bsp[q][(size_t)(n0 + bn) * EDIM + c0 + bseg * 8]);
            asm volatile("cp.async.commit_group;");
            const float4* src = (const float4*)(zbase + (size_t)(c0 + cr) * 1024 + cm);
            #pragma unroll
            for (int q = 0; q < 4; q++) {
                float4 f = src[q];
                float xs[4] = {f.x, f.y, f.z, f.w};
                __nv_bfloat16 p0[4], p1[4], p2[4];
                #pragma unroll
                for (int e = 0; e < 4; e++) {
                    p0[e] = __float2bfloat16(xs[e]); float r = xs[e] - __bfloat162float(p0[e]);
                    p1[e] = __float2bfloat16(r);     r = r - __bfloat162float(p1[e]);
                    p2[e] = __float2bfloat16(r);
                }
                uint32_t off = nbuf * AS_BUF + cr * AS_STRIDE + cm * 2 + q * 8;
                __nv_bfloat162 v;
                v = __halves2bfloat162(p0[0], p0[1]); *(uint32_t*)(smem + 0 * AS_SPLIT + off)     = *(uint32_t*)&v;
                v = __halves2bfloat162(p0[2], p0[3]); *(uint32_t*)(smem + 0 * AS_SPLIT + off + 4) = *(uint32_t*)&v;
                v = __halves2bfloat162(p1[0], p1[1]); *(uint32_t*)(smem + 1 * AS_SPLIT + off)     = *(uint32_t*)&v;
                v = __halves2bfloat162(p1[2], p1[3]); *(uint32_t*)(smem + 1 * AS_SPLIT + off + 4) = *(uint32_t*)&v;
                v = __halves2bfloat162(p2[0], p2[1]); *(uint32_t*)(smem + 2 * AS_SPLIT + off)     = *(uint32_t*)&v;
                v = __halves2bfloat162(p2[2], p2[3]); *(uint32_t*)(smem + 2 * AS_SPLIT + off + 4) = *(uint32_t*)&v;
            }
            asm volatile("cp.async.wait_group 1;");
        } else {
            asm volatile("cp.async.wait_group 0;");
        }
        __syncthreads();

        // ---- compute this chunk ----
        const uint32_t asB = sb + buf * AS_BUF;
        const uint32_t bsB = sb + BS_OFF + buf * BS_BUF;
        const int sel = lane >> 3, rr = lane & 7;
        #pragma unroll
        for (int ks = 0; ks < 2; ks++) {
            const int k0 = ks * 16;
            #pragma unroll
            for (int bj = 0; bj < 3; bj++) {
                uint32_t bb[8];
                {   // n-frags 0,1
                    uint32_t addr = bsB + bj * BS_SPLIT
                                  + (wn * 32 + (sel >> 1) * 8 + rr) * 80
                                  + (k0 + (sel & 1) * 8) * 2;
                    ldsm_x4(bb, addr);
                    ldsm_x4(bb + 4, addr + 16 * 80);   // n-frags 2,3
                }
                const int nai = 3 - bj;
                #pragma unroll
                for (int ai = 0; ai < 3; ai++) {
                    if (ai >= nai) break;
                    #pragma unroll
                    for (int i = 0; i < 4; i++) {
                        uint32_t a[4];
                        uint32_t addr = asB + ai * AS_SPLIT
                                      + (k0 + (sel >> 1) * 8 + rr) * AS_STRIDE
                                      + (wm * 64 + i * 16 + (sel & 1) * 8) * 2;
                        ldsm_x4t(a, addr);
                        #pragma unroll
                        for (int j = 0; j < 4; j++)
                            mma16816(acc[i][j], a, bb[2 * j], bb[2 * j + 1]);
                    }
                }
            }
        }
        __syncthreads();
    }

    // ---- epilogue: distances + argmin ----
    const int g = lane >> 2, tg = lane & 3;
    float cbn[8];
    #pragma unroll
    for (int j = 0; j < 4; j++) {
        cbn[2 * j]     = ((float*)(smem + CBN_OFF))[wn * 32 + j * 8 + tg * 2];
        cbn[2 * j + 1] = ((float*)(smem + CBN_OFF))[wn * 32 + j * 8 + tg * 2 + 1];
    }
    unsigned long long* kred = (unsigned long long*)(smem + KRED_OFF);
    #pragma unroll
    for (int i = 0; i < 4; i++) {
        #pragma unroll
        for (int h = 0; h < 2; h++) {
            float best = 3.4e38f; int bidx = 0;
            #pragma unroll
            for (int j = 0; j < 4; j++) {
                float d0 = cbn[2 * j]     - 2.0f * acc[i][j][h * 2];
                float d1 = cbn[2 * j + 1] - 2.0f * acc[i][j][h * 2 + 1];
                int c = n0 + wn * 32 + j * 8 + tg * 2;
                if (d0 < best) { best = d0; bidx = c; }
                if (d1 < best) { best = d1; bidx = c + 1; }
            }
            unsigned long long key = ((unsigned long long)ordf(best) << 32) | (unsigned)bidx;
            #pragma unroll
            for (int off = 1; off <= 2; off <<= 1) {
                unsigned long long o = __shfl_down_sync(0xffffffffu, key, off, 4);
                if (o < key) key = o;
            }
            if (tg == 0) kred[(wm * 64 + i * 16 + h * 8 + g) * 4 + wn] = key;
        }
    }
    __syncthreads();
    if (tid < 256) {
        unsigned long long k = kred[tid * 4];
        #pragma unroll
        for (int q = 1; q < 4; q++) {
            unsigned long long o = kred[tid * 4 + q];
            if (o < k) k = o;
        }
        atomicMin(&g_key[m0 + tid], k);
    }
}

// ---------- outputs ----------
__global__ __launch_bounds__(256) void onehot_kernel(float* __restrict__ out) {
    int r = blockIdx.x, t = threadIdx.x;
    int idx = (int)(g_key[r] & 0xFFFFFFFFu);
    int c0 = t * 4;
    float4 v;
    v.x = (idx == c0) ? 1.f : 0.f; v.y = (idx == c0 + 1) ? 1.f : 0.f;
    v.z = (idx == c0 + 2) ? 1.f : 0.f; v.w = (idx == c0 + 3) ? 1.f : 0.f;
    *(float4*)&out[(size_t)r * NUM_E + c0] = v;
}
__global__ __launch_bounds__(256) void quant_kernel(float* __restrict__ outq) {
    int i = blockIdx.x * blockDim.x + threadIdx.x;
    int flat = i * 4;
    int hw = flat & 1023, c = (flat >> 10) & 255, b = flat >> 18;
    int r0 = b * 1024 + hw;
    int4 idx4;
    idx4.x = (int)(g_key[r0] & 0xFFFFFFFFu);
    idx4.y = (int)(g_key[r0 + 1] & 0xFFFFFFFFu);
    idx4.z = (int)(g_key[r0 + 2] & 0xFFFFFFFFu);
    idx4.w = (int)(g_key[r0 + 3] & 0xFFFFFFFFu);
    const float* rowp = &g_cbT[(size_t)c * NUM_E];
    float4 v;
    v.x = rowp[idx4.x]; v.y = rowp[idx4.y]; v.z = rowp[idx4.z]; v.w = rowp[idx4.w];
    *(float4*)&outq[flat] = v;
}

extern "C" void kernel_launch(void* const* d_in, const int* in_sizes, int n_in,
                              void* d_out, int out_size) {
    const float* z  = (const float*)d_in[0];
    const float* cb = (const float*)d_in[1];
    float* out_onehot = (float*)d_out;
    float* out_q      = (float*)d_out + (size_t)NROWS * NUM_E;

    static int configured = 0;
    cudaFuncSetAttribute(vq_mma_kernel, cudaFuncAttributeMaxDynamicSharedMemorySize, SMEM_TOTAL);
    (void)configured;

    prep_kernel<<<NUM_E, 256>>>(cb);
    vq_mma_kernel<<<1024, 512, SMEM_TOTAL>>>(z);
    onehot_kernel<<<NROWS, 256>>>(out_onehot);
    quant_kernel<<<(NROWS * EDIM) / 4 / 256, 256>>>(out_q);
}

// round 6
// speedup vs baseline: 4.9559x; 1.0904x over previous
#include <cuda_runtime.h>
#include <cuda_bf16.h>
#include <cstdint>

#define NUM_E 1024
#define EDIM  256
#define NROWS 32768

// ---- device scratch ----
__device__ float g_cbnorm[NUM_E];
__device__ float g_cbT[EDIM * NUM_E];
__device__ unsigned long long g_key[NROWS];        // (ordfloat<<32)|idx
__device__ __nv_bfloat16 g_bsp[3][NUM_E * EDIM];   // codebook bf16 splits [sp][n][c]

// ---- smem layout (bytes) ----
#define AS_STRIDE 272                // 128 m * 2B + 16 pad (4-bank row step, conflict-free ldsm)
#define AS_SPLIT  (32 * AS_STRIDE)   // 8704
#define AS_BUF    (3 * AS_SPLIT)     // 26112
#define BS_OFF    (2 * AS_BUF)       // 52224
#define BS_STRIDE 80
#define BS_SPLIT  (128 * BS_STRIDE)  // 10240
#define BS_BUF    (3 * BS_SPLIT)     // 30720
#define SMEM_TOTAL (BS_OFF + 2 * BS_BUF)  // 113664  -> 2 CTAs/SM

__device__ __forceinline__ uint32_t smem_u32(const void* p) {
    uint32_t a;
    asm("{ .reg .u64 t; cvta.to.shared.u64 t, %1; cvt.u32.u64 %0, t; }" : "=r"(a) : "l"(p));
    return a;
}
__device__ __forceinline__ void cpasync16(uint32_t dst, const void* src) {
    asm volatile("cp.async.cg.shared.global [%0], [%1], 16;" :: "r"(dst), "l"(src));
}
__device__ __forceinline__ void ldsm_x4(uint32_t* r, uint32_t addr) {
    asm volatile("ldmatrix.sync.aligned.m8n8.x4.shared.b16 {%0,%1,%2,%3}, [%4];"
                 : "=r"(r[0]), "=r"(r[1]), "=r"(r[2]), "=r"(r[3]) : "r"(addr));
}
__device__ __forceinline__ void ldsm_x4t(uint32_t* r, uint32_t addr) {
    asm volatile("ldmatrix.sync.aligned.m8n8.x4.trans.shared.b16 {%0,%1,%2,%3}, [%4];"
                 : "=r"(r[0]), "=r"(r[1]), "=r"(r[2]), "=r"(r[3]) : "r"(addr));
}
__device__ __forceinline__ void mma16816(float* c, const uint32_t* a, uint32_t b0, uint32_t b1) {
    asm volatile("mma.sync.aligned.m16n8k16.row.col.f32.bf16.bf16.f32 "
                 "{%0,%1,%2,%3}, {%4,%5,%6,%7}, {%8,%9}, {%0,%1,%2,%3};"
                 : "+f"(c[0]), "+f"(c[1]), "+f"(c[2]), "+f"(c[3])
                 : "r"(a[0]), "r"(a[1]), "r"(a[2]), "r"(a[3]), "r"(b0), "r"(b1));
}
__device__ __forceinline__ unsigned ordf(float d) {
    unsigned u = __float_as_uint(d);
    return (u & 0x80000000u) ? ~u : (u | 0x80000000u);
}

// ---------- prep: norms + transpose + bf16 splits + key init ----------
__global__ __launch_bounds__(256) void prep_kernel(const float* __restrict__ cb) {
    int k = blockIdx.x, t = threadIdx.x;
    float v = cb[(size_t)k * EDIM + t];
    g_cbT[(size_t)t * NUM_E + k] = v;
    __nv_bfloat16 s0 = __float2bfloat16(v);  float r1 = v - __bfloat162float(s0);
    __nv_bfloat16 s1 = __float2bfloat16(r1); float r2 = r1 - __bfloat162float(s1);
    __nv_bfloat16 s2 = __float2bfloat16(r2);
    g_bsp[0][k * EDIM + t] = s0;
    g_bsp[1][k * EDIM + t] = s1;
    g_bsp[2][k * EDIM + t] = s2;
    if (t < 32) g_key[k * 32 + t] = ~0ull;
    float sq = v * v;
    #pragma unroll
    for (int o = 16; o; o >>= 1) sq += __shfl_down_sync(0xffffffffu, sq, o);
    __shared__ float ws[8];
    if ((t & 31) == 0) ws[t >> 5] = sq;
    __syncthreads();
    if (t == 0) {
        float s = 0.f;
        #pragma unroll
        for (int i = 0; i < 8; i++) s += ws[i];
        g_cbnorm[k] = s;
    }
}

// A-chunk convert+store helper: 32 c-rows x 128 m, 3 splits
__device__ __forceinline__ void convert_A(unsigned char* smem, uint32_t dstbase,
                                          const float* __restrict__ zsrc, int tid) {
    const int cr = tid >> 3, cm = (tid & 7) * 16;
    const float4* src = (const float4*)(zsrc + (size_t)cr * 1024 + cm);
    #pragma unroll
    for (int q = 0; q < 4; q++) {
        float4 f = src[q];
        float xs[4] = {f.x, f.y, f.z, f.w};
        __nv_bfloat16 p0[4], p1[4], p2[4];
        #pragma unroll
        for (int e = 0; e < 4; e++) {
            p0[e] = __float2bfloat16(xs[e]); float r = xs[e] - __bfloat162float(p0[e]);
            p1[e] = __float2bfloat16(r);     r = r - __bfloat162float(p1[e]);
            p2[e] = __float2bfloat16(r);
        }
        uint32_t off = dstbase + cr * AS_STRIDE + (cm + q * 4) * 2;
        __nv_bfloat162 v;
        v = __halves2bfloat162(p0[0], p0[1]); *(uint32_t*)(smem + 0 * AS_SPLIT + off)     = *(uint32_t*)&v;
        v = __halves2bfloat162(p0[2], p0[3]); *(uint32_t*)(smem + 0 * AS_SPLIT + off + 4) = *(uint32_t*)&v;
        v = __halves2bfloat162(p1[0], p1[1]); *(uint32_t*)(smem + 1 * AS_SPLIT + off)     = *(uint32_t*)&v;
        v = __halves2bfloat162(p1[2], p1[3]); *(uint32_t*)(smem + 1 * AS_SPLIT + off + 4) = *(uint32_t*)&v;
        v = __halves2bfloat162(p2[0], p2[1]); *(uint32_t*)(smem + 2 * AS_SPLIT + off)     = *(uint32_t*)&v;
        v = __halves2bfloat162(p2[2], p2[3]); *(uint32_t*)(smem + 2 * AS_SPLIT + off + 4) = *(uint32_t*)&v;
    }
}

// B-chunk cp.async: 3 splits x 128 n-rows x 64B
__device__ __forceinline__ void issue_B(uint32_t sb_dst, int n0, int c0, int tid) {
    #pragma unroll
    for (int r = 0; r < 6; r++) {
        int e = tid + r * 256;
        int seg = e & 3, rowq = e >> 2;
        int bn = rowq & 127, q = rowq >> 7;
        cpasync16(sb_dst + q * BS_SPLIT + bn * BS_STRIDE + seg * 16,
                  &g_bsp[q][(size_t)(n0 + bn) * EDIM + c0 + seg * 8]);
    }
    asm volatile("cp.async.commit_group;");
}

// ---------- main: bf16 mma.sync GEMM + fused argmin ----------
// grid = 2048 (256 mtiles x 8 ntiles), block = 256, 2 CTAs/SM
__global__ __launch_bounds__(256, 2) void vq_mma_kernel(const float* __restrict__ z) {
    extern __shared__ __align__(16) unsigned char smem[];
    const uint32_t sb = smem_u32(smem);
    const int tid = threadIdx.x;
    const int lane = tid & 31;
    const int w = tid >> 5, wm = w & 1, wn = w >> 1;   // 2 m-warps x 4 n-warps
    const int ntile = blockIdx.x & 7, mtile = blockIdx.x >> 3;
    const int m0 = mtile * 128, n0 = ntile * 128;
    const float* zbase = z + (size_t)(m0 >> 10) * (EDIM * 1024) + (m0 & 1023);

    float acc[4][4][4];
    #pragma unroll
    for (int i = 0; i < 4; i++)
        #pragma unroll
        for (int j = 0; j < 4; j++)
            #pragma unroll
            for (int e = 0; e < 4; e++) acc[i][j][e] = 0.f;

    // chunk 0 prologue
    issue_B(sb + BS_OFF, n0, 0, tid);
    convert_A(smem, 0, zbase, tid);

    const int sel = lane >> 3, rr = lane & 7;
    #pragma unroll 1
    for (int ch = 0; ch < 8; ch++) {
        const int buf = ch & 1;
        if (ch < 7) {
            const int c0 = (ch + 1) * 32, nbuf = buf ^ 1;
            issue_B(sb + BS_OFF + nbuf * BS_BUF, n0, c0, tid);
            convert_A(smem, nbuf * AS_BUF, zbase + (size_t)c0 * 1024, tid);
            asm volatile("cp.async.wait_group 1;");
        } else {
            asm volatile("cp.async.wait_group 0;");
        }
        __syncthreads();

        const uint32_t asB = sb + buf * AS_BUF;
        const uint32_t bsB = sb + BS_OFF + buf * BS_BUF;
        #pragma unroll
        for (int ks = 0; ks < 2; ks++) {
            const int k0 = ks * 16;
            // load all 3 B splits into regs (n=32, k=16 each)
            uint32_t bb[3][8];
            #pragma unroll
            for (int bj = 0; bj < 3; bj++) {
                uint32_t addr = bsB + bj * BS_SPLIT
                              + (wn * 32 + (sel >> 1) * 8 + rr) * BS_STRIDE
                              + (k0 + (sel & 1) * 8) * 2;
                ldsm_x4(bb[bj], addr);
                ldsm_x4(bb[bj] + 4, addr + 16 * BS_STRIDE);
            }
            // stream A frags once each; use against all eligible B splits
            #pragma unroll
            for (int ai = 0; ai < 3; ai++) {
                const int nbj = 3 - ai;
                #pragma unroll
                for (int i = 0; i < 4; i++) {
                    uint32_t a[4];
                    uint32_t addr = asB + ai * AS_SPLIT
                                  + (k0 + (sel >> 1) * 8 + rr) * AS_STRIDE
                                  + (wm * 64 + i * 16 + (sel & 1) * 8) * 2;
                    ldsm_x4t(a, addr);
                    #pragma unroll
                    for (int bj = 0; bj < 3; bj++) {
                        if (bj >= nbj) break;
                        #pragma unroll
                        for (int j = 0; j < 4; j++)
                            mma16816(acc[i][j], a, bb[bj][2 * j], bb[bj][2 * j + 1]);
                    }
                }
            }
        }
        __syncthreads();
    }

    // ---- epilogue: distances + argmin (kred aliases A buffer region) ----
    const int g = lane >> 2, tg = lane & 3;
    float cbn[8];
    #pragma unroll
    for (int j = 0; j < 4; j++) {
        cbn[2 * j]     = __ldg(&g_cbnorm[n0 + wn * 32 + j * 8 + tg * 2]);
        cbn[2 * j + 1] = __ldg(&g_cbnorm[n0 + wn * 32 + j * 8 + tg * 2 + 1]);
    }
    unsigned long long* kred = (unsigned long long*)smem;
    #pragma unroll
    for (int i = 0; i < 4; i++) {
        #pragma unroll
        for (int h = 0; h < 2; h++) {
            float best = 3.4e38f; int bidx = 0;
            #pragma unroll
            for (int j = 0; j < 4; j++) {
                float d0 = cbn[2 * j]     - 2.0f * acc[i][j][h * 2];
                float d1 = cbn[2 * j + 1] - 2.0f * acc[i][j][h * 2 + 1];
                int c = n0 + wn * 32 + j * 8 + tg * 2;
                if (d0 < best) { best = d0; bidx = c; }
                if (d1 < best) { best = d1; bidx = c + 1; }
            }
            unsigned long long key = ((unsigned long long)ordf(best) << 32) | (unsigned)bidx;
            #pragma unroll
            for (int off = 1; off <= 2; off <<= 1) {
                unsigned long long o = __shfl_down_sync(0xffffffffu, key, off, 4);
                if (o < key) key = o;
            }
            if (tg == 0) kred[(wm * 64 + i * 16 + h * 8 + g) * 4 + wn] = key;
        }
    }
    __syncthreads();
    if (tid < 128) {
        unsigned long long k = kred[tid * 4];
        #pragma unroll
        for (int q = 1; q < 4; q++) {
            unsigned long long o = kred[tid * 4 + q];
            if (o < k) k = o;
        }
        atomicMin(&g_key[m0 + tid], k);
    }
}

// ---------- merged outputs: blocks [0,32768) one-hot, [32768,40960) quantized ----------
__global__ __launch_bounds__(256) void out_kernel(float* __restrict__ oh, float* __restrict__ oq) {
    int bid = blockIdx.x, t = threadIdx.x;
    if (bid < 32768) {
        int idx = (int)(g_key[bid] & 0xFFFFFFFFu);
        int c0 = t * 4;
        float4 v;
        v.x = (idx == c0) ? 1.f : 0.f; v.y = (idx == c0 + 1) ? 1.f : 0.f;
        v.z = (idx == c0 + 2) ? 1.f : 0.f; v.w = (idx == c0 + 3) ? 1.f : 0.f;
        *(float4*)&oh[(size_t)bid * NUM_E + c0] = v;
    } else {
        int i = (bid - 32768) * 256 + t;
        int flat = i * 4;
        int hw = flat & 1023, c = (flat >> 10) & 255, b = flat >> 18;
        int r0 = b * 1024 + hw;
        int4 idx4;
        idx4.x = (int)(g_key[r0] & 0xFFFFFFFFu);
        idx4.y = (int)(g_key[r0 + 1] & 0xFFFFFFFFu);
        idx4.z = (int)(g_key[r0 + 2] & 0xFFFFFFFFu);
        idx4.w = (int)(g_key[r0 + 3] & 0xFFFFFFFFu);
        const float* rowp = &g_cbT[(size_t)c * NUM_E];
        float4 v;
        v.x = rowp[idx4.x]; v.y = rowp[idx4.y]; v.z = rowp[idx4.z]; v.w = rowp[idx4.w];
        *(float4*)&oq[flat] = v;
    }
}

extern "C" void kernel_launch(void* const* d_in, const int* in_sizes, int n_in,
                              void* d_out, int out_size) {
    const float* z  = (const float*)d_in[0];
    const float* cb = (const float*)d_in[1];
    float* out_onehot = (float*)d_out;
    float* out_q      = (float*)d_out + (size_t)NROWS * NUM_E;

    cudaFuncSetAttribute(vq_mma_kernel, cudaFuncAttributeMaxDynamicSharedMemorySize, SMEM_TOTAL);
    prep_kernel<<<NUM_E, 256>>>(cb);
    vq_mma_kernel<<<2048, 256, SMEM_TOTAL>>>(z);
    out_kernel<<<40960, 256>>>(out_onehot, out_q);
}